// round 5
// baseline (speedup 1.0000x reference)
#include <cuda_runtime.h>

#define SEQ    1024
#define BATCH  2048
#define HID    64
#define XCHUNK 256

typedef unsigned long long u64;

__device__ __forceinline__ u64 fma2(u64 a, u64 b, u64 c) {
    u64 d;
    asm("fma.rn.f32x2 %0, %1, %2, %3;" : "=l"(d) : "l"(a), "l"(b), "l"(c));
    return d;
}
__device__ __forceinline__ u64 pack2(float a, float b) {
    u64 r;
    asm("mov.b64 %0, {%1, %2};" : "=l"(r) : "f"(a), "f"(b));
    return r;
}
__device__ __forceinline__ float2 unpack2(u64 v) {
    float2 f;
    asm("mov.b64 {%0, %1}, %2;" : "=f"(f.x), "=f"(f.y) : "l"(v));
    return f;
}
__device__ __forceinline__ float tanhA(float x) {
    float y;
    asm("tanh.approx.f32 %0, %1;" : "=f"(y) : "f"(x));
    return y;
}
__device__ __forceinline__ float sigA(float x) {
    // sigmoid(x) = 0.5 * tanh(0.5x) + 0.5
    return fmaf(0.5f, tanhA(0.5f * x), 0.5f);
}

// Layout: 256 threads per CTA (1 batch element per CTA).
// lane group: m = warp*8 + (lane>>2)  -> hidden unit (0..63)
//             s = lane & 3            -> K-slice [16s, 16s+16)
// Each lane holds W_hh rows {m, 64+m, 128+m, 192+m} restricted to its K-slice
// (4 gates x 16 weights = 64 floats = 32 packed f32x2 regs).
// Per step: 4 LDS.128 of h-slice, 32 FFMA2, 2-level shfl.bfly all-reduce over
// the 4 K-slices, then ALL 4 lanes of a unit redundantly compute activations,
// c, h (identical -> deterministic); lane s==0 stores h. ONE __syncthreads per
// step with double-buffered h.
__global__ void __launch_bounds__(256, 2)
lstm_fused_kernel(const float* __restrict__ x,
                  const float* __restrict__ W_ih,
                  const float* __restrict__ W_hh,
                  const float* __restrict__ b_ih,
                  const float* __restrict__ b_hh,
                  const float* __restrict__ fc1_w,
                  const float* __restrict__ fc1_b,
                  const float* __restrict__ fc2_w,
                  const float* __restrict__ fc2_b,
                  float* __restrict__ out)
{
    const int b    = blockIdx.x;
    const int tid  = threadIdx.x;
    const int lane = tid & 31;
    const int m    = ((tid >> 5) << 3) + (lane >> 2);  // hidden unit 0..63
    const int s    = lane & 3;                          // K-slice 0..3

    __shared__ __align__(16) float sh_h[2][HID];  // double-buffered hidden state
    __shared__ float sh_x[XCHUNK];
    __shared__ float sh_c[HID];
    __shared__ float sh_hd[128];

    // ---- load weights: 4 gate rows x 16 K-slice floats, packed f32x2 ----
    u64 w0[8], w1[8], w2[8], w3[8];
    float wih[4], bias[4];
    {
        #pragma unroll
        for (int q = 0; q < 4; q++) {
            const int r = q * HID + m;
            const float4* wr = reinterpret_cast<const float4*>(W_hh + r * HID + s * 16);
            u64* wq = (q == 0) ? w0 : (q == 1) ? w1 : (q == 2) ? w2 : w3;
            #pragma unroll
            for (int i = 0; i < 4; i++) {
                float4 v = __ldg(wr + i);
                wq[2 * i]     = pack2(v.x, v.y);
                wq[2 * i + 1] = pack2(v.z, v.w);
            }
            wih[q]  = __ldg(W_ih + r);
            bias[q] = __ldg(b_ih + r) + __ldg(b_hh + r);
        }
    }

    // ---- init ----
    if (tid < HID) sh_h[0][tid] = 0.0f;
    float c = 0.0f;   // replicated across the 4 lanes of each unit
    int   p = 0;      // h buffer parity

    // ---- time recurrence ----
    #pragma unroll 1
    for (int t0 = 0; t0 < SEQ; t0 += XCHUNK) {
        sh_x[tid] = __ldg(x + (t0 + tid) * BATCH + b);
        __syncthreads();   // covers x staging (and h init / previous chunk)

        #pragma unroll 1
        for (int tt = 0; tt < XCHUNK; tt++) {
            const float xv = sh_x[tt];

            // ---- partial dots: this lane's 16-wide K-slice, 4 gates ----
            const ulonglong2* h2 =
                reinterpret_cast<const ulonglong2*>(&sh_h[p][s * 16]);
            u64 a0 = 0ull, a1 = 0ull, a2 = 0ull, a3 = 0ull;
            #pragma unroll
            for (int i = 0; i < 4; i++) {
                ulonglong2 hv = h2[i];   // 4 h values
                a0 = fma2(hv.x, w0[2 * i], a0);
                a1 = fma2(hv.x, w1[2 * i], a1);
                a2 = fma2(hv.x, w2[2 * i], a2);
                a3 = fma2(hv.x, w3[2 * i], a3);
                a0 = fma2(hv.y, w0[2 * i + 1], a0);
                a1 = fma2(hv.y, w1[2 * i + 1], a1);
                a2 = fma2(hv.y, w2[2 * i + 1], a2);
                a3 = fma2(hv.y, w3[2 * i + 1], a3);
            }
            float2 f0 = unpack2(a0), f1 = unpack2(a1),
                   f2 = unpack2(a2), f3 = unpack2(a3);
            float v0 = f0.x + f0.y;
            float v1 = f1.x + f1.y;
            float v2 = f2.x + f2.y;
            float v3 = f3.x + f3.y;

            // ---- all-reduce over the 4 K-slices (lanes differ only in s) ----
            v0 += __shfl_xor_sync(0xffffffffu, v0, 1);
            v1 += __shfl_xor_sync(0xffffffffu, v1, 1);
            v2 += __shfl_xor_sync(0xffffffffu, v2, 1);
            v3 += __shfl_xor_sync(0xffffffffu, v3, 1);
            v0 += __shfl_xor_sync(0xffffffffu, v0, 2);
            v1 += __shfl_xor_sync(0xffffffffu, v1, 2);
            v2 += __shfl_xor_sync(0xffffffffu, v2, 2);
            v3 += __shfl_xor_sync(0xffffffffu, v3, 2);

            // ---- gates (redundant across the 4 lanes of the unit) ----
            const float iv = sigA(v0 + fmaf(xv, wih[0], bias[0]));
            const float fv = sigA(v1 + fmaf(xv, wih[1], bias[1]));
            const float gv = tanhA(v2 + fmaf(xv, wih[2], bias[2]));
            const float ov = sigA(v3 + fmaf(xv, wih[3], bias[3]));

            c = fmaf(fv, c, iv * gv);
            const float h = ov * tanhA(c);

            if (s == 0) sh_h[p ^ 1][m] = h;
            __syncthreads();
            p ^= 1;
        }
    }

    // ---- MLP head on cell state ----
    if (s == 0) sh_c[m] = c;
    __syncthreads();

    if (tid < 128) {
        const float* fw = fc1_w + tid * HID;
        float acc = __ldg(fc1_b + tid);
        #pragma unroll
        for (int k = 0; k < HID; k++) acc = fmaf(__ldg(fw + k), sh_c[k], acc);
        sh_hd[tid] = acc;
    }
    __syncthreads();

    if (tid < 5) {
        const float* fw = fc2_w + tid * 128;
        float acc = __ldg(fc2_b + tid);
        #pragma unroll
        for (int k = 0; k < 128; k++) acc = fmaf(__ldg(fw + k), sh_hd[k], acc);
        out[b * 5 + tid] = acc;
    }
}

extern "C" void kernel_launch(void* const* d_in, const int* in_sizes, int n_in,
                              void* d_out, int out_size)
{
    const float* x     = (const float*)d_in[0];
    const float* W_ih  = (const float*)d_in[1];
    const float* W_hh  = (const float*)d_in[2];
    const float* b_ih  = (const float*)d_in[3];
    const float* b_hh  = (const float*)d_in[4];
    const float* fc1_w = (const float*)d_in[5];
    const float* fc1_b = (const float*)d_in[6];
    const float* fc2_w = (const float*)d_in[7];
    const float* fc2_b = (const float*)d_in[8];
    float* out = (float*)d_out;

    lstm_fused_kernel<<<BATCH, 256>>>(x, W_ih, W_hh, b_ih, b_hh,
                                      fc1_w, fc1_b, fc2_w, fc2_b, out);
}